// round 8
// baseline (speedup 1.0000x reference)
#include <cuda_runtime.h>
#include <math.h>

// Problem constants (fixed by reference: B=32768, D=512)
#define BSZ 32768
#define DSZ 512
#define ROWS_PER_BLOCK 32
#define NBLOCKS (BSZ / ROWS_PER_BLOCK)   // 1024 -> single co-resident wave
#define NTHREADS 256
#define F4_PER_ROW (DSZ / 4)             // 128
#define ITERS ((ROWS_PER_BLOCK * F4_PER_ROW) / NTHREADS)  // 16

__device__ float g_partials[NBLOCKS];
__device__ int   g_count;   // zero-init; reset to 0 by last block each launch

__global__ void __launch_bounds__(NTHREADS)
fused_loss_kernel(const float4* __restrict__ inp,
                  const float4* __restrict__ lab,
                  const float*  __restrict__ ea,
                  const int*    __restrict__ attribute,
                  const float*  __restrict__ attribute_num,
                  float* __restrict__ out) {
    __shared__ float sw[ROWS_PER_BLOCK];
    __shared__ float sdata[NTHREADS];

    const int tid = threadIdx.x;
    const int row0 = blockIdx.x * ROWS_PER_BLOCK;

    // ---- per-row weights for this block's 32 rows (threads 0..31) ----
    if (tid < ROWS_PER_BLOCK) {
        const int b = row0 + tid;
        float s = attribute_num[0] + attribute_num[1] + attribute_num[2]
                + attribute_num[3] + attribute_num[4] + attribute_num[5];
        float attr_w = 0.0f;
#pragma unroll
        for (int j = 0; j < 6; j++) {
            if (attribute[b * 6 + j] == 1) attr_w += s / attribute_num[j];
        }
        float angle_w = 3.0f - cosf(ea[b * 3 + 0])
                             - cosf(ea[b * 3 + 1])
                             - cosf(ea[b * 3 + 2]);
        sw[tid] = angle_w * attr_w;
    }
    __syncthreads();

    // ---- main HBM-bound loop: 16 iterations, unroll 4 (keeps regs ~32
    //      so 8 blocks/SM resident -> 1184 >= 1024 -> one wave) ----
    const int base = row0 * F4_PER_ROW + tid;    // float4 index
    const int wbase = tid >> 7;                  // 0 or 1 (128 float4/row)
    float acc = 0.0f;
#pragma unroll 4
    for (int k = 0; k < ITERS; k++) {
        const int i = base + k * NTHREADS;
        const float4 a = __ldcs(&inp[i]);
        const float4 b = __ldcs(&lab[i]);
        const float w = sw[k * 2 + wbase];
        const float dx = a.x - b.x;
        const float dy = a.y - b.y;
        const float dz = a.z - b.z;
        const float dw = a.w - b.w;
        acc += w * (dx * dx + dy * dy + dz * dz + dw * dw);
    }

    // ---- block tree-reduce ----
    sdata[tid] = acc;
    __syncthreads();
#pragma unroll
    for (int off = NTHREADS / 2; off >= 32; off >>= 1) {
        if (tid < off) sdata[tid] += sdata[tid + off];
        __syncthreads();
    }
    if (tid < 32) {
        float v = sdata[tid];
#pragma unroll
        for (int off = 16; off > 0; off >>= 1)
            v += __shfl_down_sync(0xFFFFFFFF, v, off);
        if (tid == 0) g_partials[blockIdx.x] = v;
    }

    // ---- last-block-done final reduce (deterministic fixed-order sum) ----
    __shared__ bool is_last;
    if (tid == 0) {
        __threadfence();                          // publish g_partials
        int old = atomicAdd(&g_count, 1);
        is_last = (old == NBLOCKS - 1);
    }
    __syncthreads();
    if (!is_last) return;

    float v = 0.0f;
#pragma unroll
    for (int k = 0; k < NBLOCKS / NTHREADS; k++)  // 4 fixed-order terms
        v += g_partials[tid + k * NTHREADS];
    sdata[tid] = v;
    __syncthreads();
#pragma unroll
    for (int off = NTHREADS / 2; off >= 32; off >>= 1) {
        if (tid < off) sdata[tid] += sdata[tid + off];
        __syncthreads();
    }
    if (tid < 32) {
        float s2 = sdata[tid];
#pragma unroll
        for (int off = 16; off > 0; off >>= 1)
            s2 += __shfl_down_sync(0xFFFFFFFF, s2, off);
        if (tid == 0) {
            out[0] = s2 * (1.0f / (float)(BSZ * DSZ));
            g_count = 0;   // reset so graph replay is deterministic
        }
    }
}

// ---------------------------------------------------------------------------
// kernel_launch — input order: inp, label, ea, attribute, attribute_num,
// batch_size
// ---------------------------------------------------------------------------
extern "C" void kernel_launch(void* const* d_in, const int* in_sizes, int n_in,
                              void* d_out, int out_size) {
    const float* inp  = (const float*)d_in[0];
    const float* lab  = (const float*)d_in[1];
    const float* ea   = (const float*)d_in[2];
    const int*   attr = (const int*)d_in[3];
    const float* anum = (const float*)d_in[4];
    float* out = (float*)d_out;

    fused_loss_kernel<<<NBLOCKS, NTHREADS>>>((const float4*)inp,
                                             (const float4*)lab,
                                             ea, attr, anum, out);
}

// round 9
// speedup vs baseline: 1.1444x; 1.1444x over previous
#include <cuda_runtime.h>
#include <math.h>

// Problem constants (fixed by reference: B=32768, D=512)
#define BSZ 32768
#define DSZ 512
#define ROWS_PER_BLOCK 16
#define NBLOCKS (BSZ / ROWS_PER_BLOCK)   // 2048
#define NTHREADS 256
#define F4_PER_ROW (DSZ / 4)             // 128
#define NSTAGES 8                        // 2048 float4 per block / 256 threads
#define DEPTH 3                          // cp.async pipeline depth

__device__ float g_partials[NBLOCKS];
__device__ int   g_count;   // zero-init; reset to 0 by last block each launch

__device__ __forceinline__ void cp_async16(void* smem_dst, const void* gmem_src) {
    unsigned saddr = (unsigned)__cvta_generic_to_shared(smem_dst);
    asm volatile("cp.async.cg.shared.global [%0], [%1], 16;\n"
                 :: "r"(saddr), "l"(gmem_src));
}
#define CP_COMMIT()  asm volatile("cp.async.commit_group;\n" ::: "memory")
#define CP_WAIT(N)   asm volatile("cp.async.wait_group %0;\n" :: "n"(N) : "memory")

__global__ void __launch_bounds__(NTHREADS)
fused_loss_kernel(const float4* __restrict__ inp,
                  const float4* __restrict__ lab,
                  const float*  __restrict__ ea,
                  const int*    __restrict__ attribute,
                  const float*  __restrict__ attribute_num,
                  float* __restrict__ out) {
    __shared__ float4 sa[DEPTH][NTHREADS];   // 12 KB
    __shared__ float4 sb[DEPTH][NTHREADS];   // 12 KB
    __shared__ float  sw[ROWS_PER_BLOCK];
    __shared__ float  sdata[NTHREADS];

    const int tid = threadIdx.x;
    const int row0 = blockIdx.x * ROWS_PER_BLOCK;
    const float4* ga = inp + row0 * F4_PER_ROW + tid;
    const float4* gb = lab + row0 * F4_PER_ROW + tid;

    // ---- issue first DEPTH stages immediately (hide behind weight math) ----
#pragma unroll
    for (int k = 0; k < DEPTH; k++) {
        cp_async16(&sa[k][tid], ga + k * NTHREADS);
        cp_async16(&sb[k][tid], gb + k * NTHREADS);
        CP_COMMIT();
    }

    // ---- per-row weights for this block's 16 rows (threads 0..15) ----
    if (tid < ROWS_PER_BLOCK) {
        const int b = row0 + tid;
        float s = attribute_num[0] + attribute_num[1] + attribute_num[2]
                + attribute_num[3] + attribute_num[4] + attribute_num[5];
        float attr_w = 0.0f;
#pragma unroll
        for (int j = 0; j < 6; j++) {
            if (attribute[b * 6 + j] == 1) attr_w += s / attribute_num[j];
        }
        float angle_w = 3.0f - cosf(ea[b * 3 + 0])
                             - cosf(ea[b * 3 + 1])
                             - cosf(ea[b * 3 + 2]);
        sw[tid] = angle_w * attr_w;
    }
    __syncthreads();   // sw visible to all; pipeline unaffected

    const int wbase = tid >> 7;              // 0 or 1 (128 float4 per row)
    float acc = 0.0f;

    // ---- steady state: consume stage k, refill slot with stage k+DEPTH ----
#pragma unroll
    for (int k = 0; k < NSTAGES - DEPTH; k++) {   // k = 0..4
        CP_WAIT(DEPTH - 1);                       // stage k complete
        const int slot = k % DEPTH;
        const float4 a = sa[slot][tid];
        const float4 b = sb[slot][tid];
        const float w = sw[k * 2 + wbase];
        const float dx = a.x - b.x, dy = a.y - b.y;
        const float dz = a.z - b.z, dw = a.w - b.w;
        acc += w * (dx * dx + dy * dy + dz * dz + dw * dw);
        // refill: per-thread slot reuse; LDS above already sampled (in-order
        // smem issue per thread), cp.async write lands much later. No barrier.
        cp_async16(&sa[slot][tid], ga + (k + DEPTH) * NTHREADS);
        cp_async16(&sb[slot][tid], gb + (k + DEPTH) * NTHREADS);
        CP_COMMIT();
    }
    // ---- drain: stages 5,6,7 with decreasing allowed-outstanding ----
    {
        CP_WAIT(2);
        const float4 a = sa[5 % DEPTH][tid], b = sb[5 % DEPTH][tid];
        const float w = sw[5 * 2 + wbase];
        const float dx = a.x - b.x, dy = a.y - b.y;
        const float dz = a.z - b.z, dw = a.w - b.w;
        acc += w * (dx * dx + dy * dy + dz * dz + dw * dw);
    }
    {
        CP_WAIT(1);
        const float4 a = sa[6 % DEPTH][tid], b = sb[6 % DEPTH][tid];
        const float w = sw[6 * 2 + wbase];
        const float dx = a.x - b.x, dy = a.y - b.y;
        const float dz = a.z - b.z, dw = a.w - b.w;
        acc += w * (dx * dx + dy * dy + dz * dz + dw * dw);
    }
    {
        CP_WAIT(0);
        const float4 a = sa[7 % DEPTH][tid], b = sb[7 % DEPTH][tid];
        const float w = sw[7 * 2 + wbase];
        const float dx = a.x - b.x, dy = a.y - b.y;
        const float dz = a.z - b.z, dw = a.w - b.w;
        acc += w * (dx * dx + dy * dy + dz * dz + dw * dw);
    }

    // ---- block tree-reduce ----
    sdata[tid] = acc;
    __syncthreads();
#pragma unroll
    for (int off = NTHREADS / 2; off >= 32; off >>= 1) {
        if (tid < off) sdata[tid] += sdata[tid + off];
        __syncthreads();
    }
    if (tid < 32) {
        float v = sdata[tid];
#pragma unroll
        for (int off = 16; off > 0; off >>= 1)
            v += __shfl_down_sync(0xFFFFFFFF, v, off);
        if (tid == 0) g_partials[blockIdx.x] = v;
    }

    // ---- last-block-done final reduce (deterministic fixed-order sum) ----
    __shared__ bool is_last;
    if (tid == 0) {
        __threadfence();                          // publish g_partials
        int old = atomicAdd(&g_count, 1);
        is_last = (old == NBLOCKS - 1);
    }
    __syncthreads();
    if (!is_last) return;

    float v = 0.0f;
#pragma unroll
    for (int k = 0; k < NBLOCKS / NTHREADS; k++)  // 8 fixed-order terms
        v += g_partials[tid + k * NTHREADS];
    sdata[tid] = v;
    __syncthreads();
#pragma unroll
    for (int off = NTHREADS / 2; off >= 32; off >>= 1) {
        if (tid < off) sdata[tid] += sdata[tid + off];
        __syncthreads();
    }
    if (tid < 32) {
        float s2 = sdata[tid];
#pragma unroll
        for (int off = 16; off > 0; off >>= 1)
            s2 += __shfl_down_sync(0xFFFFFFFF, s2, off);
        if (tid == 0) {
            out[0] = s2 * (1.0f / (float)(BSZ * DSZ));
            g_count = 0;   // reset so graph replay is deterministic
        }
    }
}

// ---------------------------------------------------------------------------
// kernel_launch — input order: inp, label, ea, attribute, attribute_num,
// batch_size
// ---------------------------------------------------------------------------
extern "C" void kernel_launch(void* const* d_in, const int* in_sizes, int n_in,
                              void* d_out, int out_size) {
    const float* inp  = (const float*)d_in[0];
    const float* lab  = (const float*)d_in[1];
    const float* ea   = (const float*)d_in[2];
    const int*   attr = (const int*)d_in[3];
    const float* anum = (const float*)d_in[4];
    float* out = (float*)d_out;

    fused_loss_kernel<<<NBLOCKS, NTHREADS>>>((const float4*)inp,
                                             (const float4*)lab,
                                             ea, attr, anum, out);
}

// round 10
// speedup vs baseline: 1.3818x; 1.2075x over previous
#include <cuda_runtime.h>
#include <math.h>

// Problem constants (fixed by reference: B=32768, D=512)
#define BSZ 32768
#define DSZ 512
#define ROWS_PER_BLOCK 16
#define NBLOCKS (BSZ / ROWS_PER_BLOCK)   // 2048
#define NTHREADS 256
#define F4_PER_ROW (DSZ / 4)             // 128
#define NSTAGES 8                        // 2048 float4 per block / 256 threads
#define DEPTH 3                          // cp.async pipeline depth (inp only)

__device__ float g_partials[NBLOCKS];
__device__ int   g_count;   // zero-init; reset to 0 by last block each launch

__device__ __forceinline__ void cp_async16(void* smem_dst, const void* gmem_src) {
    unsigned saddr = (unsigned)__cvta_generic_to_shared(smem_dst);
    asm volatile("cp.async.cg.shared.global [%0], [%1], 16;\n"
                 :: "r"(saddr), "l"(gmem_src));
}
#define CP_COMMIT()  asm volatile("cp.async.commit_group;\n" ::: "memory")
#define CP_WAIT(N)   asm volatile("cp.async.wait_group %0;\n" :: "n"(N) : "memory")

__global__ void __launch_bounds__(NTHREADS)
fused_loss_kernel(const float4* __restrict__ inp,
                  const float4* __restrict__ lab,
                  const float*  __restrict__ ea,
                  const int*    __restrict__ attribute,
                  const float*  __restrict__ attribute_num,
                  float* __restrict__ out) {
    __shared__ float4 sa[DEPTH][NTHREADS];   // 12 KB (inp pipeline only)
    __shared__ float  sw[ROWS_PER_BLOCK];
    __shared__ float  sdata[NTHREADS];

    const int tid = threadIdx.x;
    const int row0 = blockIdx.x * ROWS_PER_BLOCK;
    const float4* ga = inp + row0 * F4_PER_ROW + tid;
    const float4* gb = lab + row0 * F4_PER_ROW + tid;

    // ---- inp: issue first DEPTH pipeline stages immediately ----
#pragma unroll
    for (int k = 0; k < DEPTH; k++) {
        cp_async16(&sa[k][tid], ga + k * NTHREADS);
        CP_COMMIT();
    }
    // ---- label: register prefetch, distance 2 ----
    float4 b0 = __ldcs(gb + 0 * NTHREADS);
    float4 b1 = __ldcs(gb + 1 * NTHREADS);

    // ---- per-row weights for this block's 16 rows (threads 0..15) ----
    if (tid < ROWS_PER_BLOCK) {
        const int b = row0 + tid;
        float s = attribute_num[0] + attribute_num[1] + attribute_num[2]
                + attribute_num[3] + attribute_num[4] + attribute_num[5];
        float attr_w = 0.0f;
#pragma unroll
        for (int j = 0; j < 6; j++) {
            if (attribute[b * 6 + j] == 1) attr_w += s / attribute_num[j];
        }
        float angle_w = 3.0f - cosf(ea[b * 3 + 0])
                             - cosf(ea[b * 3 + 1])
                             - cosf(ea[b * 3 + 2]);
        sw[tid] = angle_w * attr_w;
    }
    __syncthreads();   // publish sw; async pipelines unaffected

    const int wbase = tid >> 7;              // 0 or 1 (128 float4 per row)
    float acc = 0.0f;

    // ---- steady state: k = 0..4 ----
#pragma unroll
    for (int k = 0; k < NSTAGES - DEPTH; k++) {
        CP_WAIT(DEPTH - 1);                       // inp stage k landed
        const int slot = k % DEPTH;
        const float4 a = sa[slot][tid];
        const float w = sw[k * 2 + wbase];
        const float dx = a.x - b0.x, dy = a.y - b0.y;
        const float dz = a.z - b0.z, dw = a.w - b0.w;
        acc += w * (dx * dx + dy * dy + dz * dz + dw * dw);
        // roll label prefetch (k+2 <= 6 here, always in range)
        b0 = b1;
        b1 = __ldcs(gb + (k + 2) * NTHREADS);
        // refill inp pipeline slot with stage k+DEPTH (<= 7, in range)
        cp_async16(&sa[slot][tid], ga + (k + DEPTH) * NTHREADS);
        CP_COMMIT();
    }
    // ---- drain: stages 5, 6, 7 ----
    {
        CP_WAIT(2);
        const float4 a = sa[5 % DEPTH][tid];
        const float w = sw[5 * 2 + wbase];
        const float dx = a.x - b0.x, dy = a.y - b0.y;
        const float dz = a.z - b0.z, dw = a.w - b0.w;
        acc += w * (dx * dx + dy * dy + dz * dz + dw * dw);
        b0 = b1;
        b1 = __ldcs(gb + 7 * NTHREADS);
    }
    {
        CP_WAIT(1);
        const float4 a = sa[6 % DEPTH][tid];
        const float w = sw[6 * 2 + wbase];
        const float dx = a.x - b0.x, dy = a.y - b0.y;
        const float dz = a.z - b0.z, dw = a.w - b0.w;
        acc += w * (dx * dx + dy * dy + dz * dz + dw * dw);
        b0 = b1;
    }
    {
        CP_WAIT(0);
        const float4 a = sa[7 % DEPTH][tid];
        const float w = sw[7 * 2 + wbase];
        const float dx = a.x - b0.x, dy = a.y - b0.y;
        const float dz = a.z - b0.z, dw = a.w - b0.w;
        acc += w * (dx * dx + dy * dy + dz * dz + dw * dw);
    }

    // ---- block tree-reduce ----
    sdata[tid] = acc;
    __syncthreads();
#pragma unroll
    for (int off = NTHREADS / 2; off >= 32; off >>= 1) {
        if (tid < off) sdata[tid] += sdata[tid + off];
        __syncthreads();
    }
    if (tid < 32) {
        float v = sdata[tid];
#pragma unroll
        for (int off = 16; off > 0; off >>= 1)
            v += __shfl_down_sync(0xFFFFFFFF, v, off);
        if (tid == 0) g_partials[blockIdx.x] = v;
    }

    // ---- last-block-done final reduce (deterministic fixed-order sum) ----
    __shared__ bool is_last;
    if (tid == 0) {
        __threadfence();                          // publish g_partials
        int old = atomicAdd(&g_count, 1);
        is_last = (old == NBLOCKS - 1);
    }
    __syncthreads();
    if (!is_last) return;

    float v = 0.0f;
#pragma unroll
    for (int k = 0; k < NBLOCKS / NTHREADS; k++)  // 8 fixed-order terms
        v += g_partials[tid + k * NTHREADS];
    sdata[tid] = v;
    __syncthreads();
#pragma unroll
    for (int off = NTHREADS / 2; off >= 32; off >>= 1) {
        if (tid < off) sdata[tid] += sdata[tid + off];
        __syncthreads();
    }
    if (tid < 32) {
        float s2 = sdata[tid];
#pragma unroll
        for (int off = 16; off > 0; off >>= 1)
            s2 += __shfl_down_sync(0xFFFFFFFF, s2, off);
        if (tid == 0) {
            out[0] = s2 * (1.0f / (float)(BSZ * DSZ));
            g_count = 0;   // reset so graph replay is deterministic
        }
    }
}

// ---------------------------------------------------------------------------
// kernel_launch — input order: inp, label, ea, attribute, attribute_num,
// batch_size
// ---------------------------------------------------------------------------
extern "C" void kernel_launch(void* const* d_in, const int* in_sizes, int n_in,
                              void* d_out, int out_size) {
    const float* inp  = (const float*)d_in[0];
    const float* lab  = (const float*)d_in[1];
    const float* ea   = (const float*)d_in[2];
    const int*   attr = (const int*)d_in[3];
    const float* anum = (const float*)d_in[4];
    float* out = (float*)d_out;

    fused_loss_kernel<<<NBLOCKS, NTHREADS>>>((const float4*)inp,
                                             (const float4*)lab,
                                             ea, attr, anum, out);
}

// round 11
// speedup vs baseline: 1.4938x; 1.0810x over previous
#include <cuda_runtime.h>
#include <math.h>

// Problem constants (fixed by reference: B=32768, D=512)
#define BSZ 32768
#define DSZ 512
#define ROWS_PER_BLOCK 16
#define NBLOCKS (BSZ / ROWS_PER_BLOCK)   // 2048
#define NTHREADS 256
#define F4_PER_ROW (DSZ / 4)             // 128
#define NSTAGES 8                        // 2048 float4 per block / 256 threads
#define DEPTH 4                          // cp.async pipeline depth (inp only)

__device__ float g_partials[NBLOCKS];
__device__ int   g_count;   // zero-init; reset to 0 by last block each launch

__device__ __forceinline__ void cp_async16(void* smem_dst, const void* gmem_src) {
    unsigned saddr = (unsigned)__cvta_generic_to_shared(smem_dst);
    asm volatile("cp.async.cg.shared.global [%0], [%1], 16;\n"
                 :: "r"(saddr), "l"(gmem_src));
}
#define CP_COMMIT()  asm volatile("cp.async.commit_group;\n" ::: "memory")
#define CP_WAIT(N)   asm volatile("cp.async.wait_group %0;\n" :: "n"(N) : "memory")

__global__ void __launch_bounds__(NTHREADS)
fused_loss_kernel(const float4* __restrict__ inp,
                  const float4* __restrict__ lab,
                  const float*  __restrict__ ea,
                  const int*    __restrict__ attribute,
                  const float*  __restrict__ attribute_num,
                  float* __restrict__ out) {
    __shared__ float4 sa[DEPTH][NTHREADS];   // 16 KB (inp pipeline only)
    __shared__ float  sw[ROWS_PER_BLOCK];
    __shared__ float  sdata[NTHREADS];

    const int tid = threadIdx.x;
    const int row0 = blockIdx.x * ROWS_PER_BLOCK;
    const float4* ga = inp + row0 * F4_PER_ROW + tid;
    const float4* gb = lab + row0 * F4_PER_ROW + tid;

    // ---- inp: issue first DEPTH pipeline stages immediately ----
#pragma unroll
    for (int k = 0; k < DEPTH; k++) {
        cp_async16(&sa[k][tid], ga + k * NTHREADS);
        CP_COMMIT();
    }
    // ---- label: register prefetch, distance 3 ----
    float4 b0 = __ldcs(gb + 0 * NTHREADS);
    float4 b1 = __ldcs(gb + 1 * NTHREADS);
    float4 b2 = __ldcs(gb + 2 * NTHREADS);

    // ---- per-row weights for this block's 16 rows (threads 0..15) ----
    if (tid < ROWS_PER_BLOCK) {
        const int b = row0 + tid;
        float s = attribute_num[0] + attribute_num[1] + attribute_num[2]
                + attribute_num[3] + attribute_num[4] + attribute_num[5];
        float attr_w = 0.0f;
#pragma unroll
        for (int j = 0; j < 6; j++) {
            if (attribute[b * 6 + j] == 1) attr_w += s / attribute_num[j];
        }
        float angle_w = 3.0f - cosf(ea[b * 3 + 0])
                             - cosf(ea[b * 3 + 1])
                             - cosf(ea[b * 3 + 2]);
        sw[tid] = angle_w * attr_w;
    }
    __syncthreads();   // publish sw; async pipelines unaffected

    const int wbase = tid >> 7;              // 0 or 1 (128 float4 per row)
    float acc = 0.0f;

    // ---- steady state: k = 0..3 (consume stage k, refill stage k+DEPTH) ----
#pragma unroll
    for (int k = 0; k < NSTAGES - DEPTH; k++) {
        CP_WAIT(DEPTH - 1);                       // inp stage k landed
        const int slot = k % DEPTH;
        const float4 a = sa[slot][tid];
        const float w = sw[k * 2 + wbase];
        const float dx = a.x - b0.x, dy = a.y - b0.y;
        const float dz = a.z - b0.z, dw = a.w - b0.w;
        acc += w * (dx * dx + dy * dy + dz * dz + dw * dw);
        // roll label prefetch (k+3 <= 6 here, always in range)
        b0 = b1; b1 = b2;
        b2 = __ldcs(gb + (k + 3) * NTHREADS);
        // refill inp pipeline slot with stage k+DEPTH (<= 7, in range)
        cp_async16(&sa[slot][tid], ga + (k + DEPTH) * NTHREADS);
        CP_COMMIT();
    }
    // ---- drain: stages 4..7 with decreasing allowed-outstanding ----
    {
        CP_WAIT(3);
        const float4 a = sa[4 % DEPTH][tid];
        const float w = sw[4 * 2 + wbase];
        const float dx = a.x - b0.x, dy = a.y - b0.y;
        const float dz = a.z - b0.z, dw = a.w - b0.w;
        acc += w * (dx * dx + dy * dy + dz * dz + dw * dw);
        b0 = b1; b1 = b2;
        b2 = __ldcs(gb + 7 * NTHREADS);
    }
    {
        CP_WAIT(2);
        const float4 a = sa[5 % DEPTH][tid];
        const float w = sw[5 * 2 + wbase];
        const float dx = a.x - b0.x, dy = a.y - b0.y;
        const float dz = a.z - b0.z, dw = a.w - b0.w;
        acc += w * (dx * dx + dy * dy + dz * dz + dw * dw);
        b0 = b1; b1 = b2;
    }
    {
        CP_WAIT(1);
        const float4 a = sa[6 % DEPTH][tid];
        const float w = sw[6 * 2 + wbase];
        const float dx = a.x - b0.x, dy = a.y - b0.y;
        const float dz = a.z - b0.z, dw = a.w - b0.w;
        acc += w * (dx * dx + dy * dy + dz * dz + dw * dw);
        b0 = b1;
    }
    {
        CP_WAIT(0);
        const float4 a = sa[7 % DEPTH][tid];
        const float w = sw[7 * 2 + wbase];
        const float dx = a.x - b0.x, dy = a.y - b0.y;
        const float dz = a.z - b0.z, dw = a.w - b0.w;
        acc += w * (dx * dx + dy * dy + dz * dz + dw * dw);
    }

    // ---- block tree-reduce ----
    sdata[tid] = acc;
    __syncthreads();
#pragma unroll
    for (int off = NTHREADS / 2; off >= 32; off >>= 1) {
        if (tid < off) sdata[tid] += sdata[tid + off];
        __syncthreads();
    }
    if (tid < 32) {
        float v = sdata[tid];
#pragma unroll
        for (int off = 16; off > 0; off >>= 1)
            v += __shfl_down_sync(0xFFFFFFFF, v, off);
        if (tid == 0) g_partials[blockIdx.x] = v;
    }

    // ---- last-block-done final reduce (deterministic fixed-order sum) ----
    __shared__ bool is_last;
    if (tid == 0) {
        __threadfence();                          // publish g_partials
        int old = atomicAdd(&g_count, 1);
        is_last = (old == NBLOCKS - 1);
    }
    __syncthreads();
    if (!is_last) return;

    float v = 0.0f;
#pragma unroll
    for (int k = 0; k < NBLOCKS / NTHREADS; k++)  // 8 fixed-order terms
        v += g_partials[tid + k * NTHREADS];
    sdata[tid] = v;
    __syncthreads();
#pragma unroll
    for (int off = NTHREADS / 2; off >= 32; off >>= 1) {
        if (tid < off) sdata[tid] += sdata[tid + off];
        __syncthreads();
    }
    if (tid < 32) {
        float s2 = sdata[tid];
#pragma unroll
        for (int off = 16; off > 0; off >>= 1)
            s2 += __shfl_down_sync(0xFFFFFFFF, s2, off);
        if (tid == 0) {
            out[0] = s2 * (1.0f / (float)(BSZ * DSZ));
            g_count = 0;   // reset so graph replay is deterministic
        }
    }
}

// ---------------------------------------------------------------------------
// kernel_launch — input order: inp, label, ea, attribute, attribute_num,
// batch_size
// ---------------------------------------------------------------------------
extern "C" void kernel_launch(void* const* d_in, const int* in_sizes, int n_in,
                              void* d_out, int out_size) {
    const float* inp  = (const float*)d_in[0];
    const float* lab  = (const float*)d_in[1];
    const float* ea   = (const float*)d_in[2];
    const int*   attr = (const int*)d_in[3];
    const float* anum = (const float*)d_in[4];
    float* out = (float*)d_out;

    fused_loss_kernel<<<NBLOCKS, NTHREADS>>>((const float4*)inp,
                                             (const float4*)lab,
                                             ea, attr, anum, out);
}